// round 12
// baseline (speedup 1.0000x reference)
#include <cuda_runtime.h>
#include <cuda_fp16.h>
#include <cstdint>
#include <math.h>

// ---------------------------------------------------------------------------
// Problem constants
// ---------------------------------------------------------------------------
#define TSEQ 2048
#define DIMC 2048
#define NH   16
#define NKV  4
#define HD   128
#define QKVN 3072
#define KOFF 2048
#define VOFF 2560

// ---------------------------------------------------------------------------
// Scratch (device globals — allocation-free per harness rules)
// ---------------------------------------------------------------------------
__device__ __half g_x[TSEQ * DIMC];       // fp16 x
__device__ __half g_wqkv[DIMC * QKVN];    // fp16 W_qkv (natural [K,N])
__device__ __half g_wo[DIMC * DIMC];      // fp16 W_o   (natural [K,N])
__device__ __half g_qkv[TSEQ * QKVN];     // qkv (fp16)
__device__ __half g_attn[TSEQ * DIMC];    // attn out (fp16)

// ---------------------------------------------------------------------------
// Helpers
// ---------------------------------------------------------------------------
__device__ __forceinline__ uint32_t smem_u32(const void* p) {
    uint32_t a;
    asm("{ .reg .u64 t; cvta.to.shared.u64 t, %1; cvt.u32.u64 %0, t; }" : "=r"(a) : "l"(p));
    return a;
}

#define CP_ASYNC16(dst, src) \
    asm volatile("cp.async.cg.shared.global [%0], [%1], 16;" :: "r"(dst), "l"(src) : "memory")
#define CP_COMMIT() asm volatile("cp.async.commit_group;" ::: "memory")
#define CP_WAIT(n)  asm volatile("cp.async.wait_group %0;" :: "n"(n) : "memory")

#define MMA_F16(c, a, b)                                                       \
    asm volatile(                                                              \
        "mma.sync.aligned.m16n8k16.row.col.f32.f16.f16.f32 "                   \
        "{%0,%1,%2,%3}, {%4,%5,%6,%7}, {%8,%9}, {%0,%1,%2,%3};"                \
        : "+f"((c)[0]), "+f"((c)[1]), "+f"((c)[2]), "+f"((c)[3])               \
        : "r"((a)[0]), "r"((a)[1]), "r"((a)[2]), "r"((a)[3]),                  \
          "r"((b)[0]), "r"((b)[1]))

#define LDSM_X4(r, addr)                                                       \
    asm volatile("ldmatrix.sync.aligned.m8n8.x4.shared.b16 {%0,%1,%2,%3}, [%4];" \
        : "=r"((r)[0]), "=r"((r)[1]), "=r"((r)[2]), "=r"((r)[3]) : "r"(addr))

#define LDSM_X4_T(r, addr)                                                     \
    asm volatile("ldmatrix.sync.aligned.m8n8.x4.trans.shared.b16 {%0,%1,%2,%3}, [%4];" \
        : "=r"((r)[0]), "=r"((r)[1]), "=r"((r)[2]), "=r"((r)[3]) : "r"(addr))

#define STSU32(addr, v) \
    asm volatile("st.shared.u32 [%0], %1;" :: "r"(addr), "r"(v) : "memory")

__device__ __forceinline__ uint32_t pack_h2(float a, float b) {
    __half2 h = __floats2half2_rn(a, b);
    return *(uint32_t*)&h;
}

// ---------------------------------------------------------------------------
// Dense fp16 GEMM: C[128,128] tile = A[128,K] @ B[K,N] (B natural row-major).
// 512 threads, 16 warps (4M x 4N), warp tile 32x32 -> 4 warps/SMSP with
// uncapped registers (acc = 32 floats/thread). 4-stage cp.async ring.
// A: 128 rows x 128B (XOR swizzle, normal ldmatrix).
// B: 64 k-rows x 256B (per-128B swizzle, trans ldmatrix).
// ---------------------------------------------------------------------------
#define STAGES 4
#define ABYTES (128 * 128)      // 16KB
#define BBYTES (64 * 256)       // 16KB
#define STAGEB (ABYTES + BBYTES)

__global__ void __launch_bounds__(512, 1) gemm_h(
    const __half* __restrict__ A, int lda,
    const __half* __restrict__ B, int ldb,
    void* __restrict__ Cv, int ldc,
    int K, int outHalf)
{
    extern __shared__ char smem[];
    const uint32_t smemBase = smem_u32(smem);

    const int bx = blockIdx.x, by = blockIdx.y;
    const int m0 = by * 128;
    const int n0 = bx * 128;
    const int tid = threadIdx.x;
    const int wid = tid >> 5, lane = tid & 31;
    const int g = lane >> 2, tg = lane & 3;
    const int wm = (wid & 3) * 32;
    const int wn = (wid >> 2) * 32;
    const int nkt = K >> 6;   // 64 k per stage

    // Loaders: 1024 16B units per operand, 2 per thread (512 threads)
    int larow[2], lau8[2], lbrow[2], lbu8[2];
    uint32_t lasw[2], lbsw[2];
#pragma unroll
    for (int i = 0; i < 2; i++) {
        int id = tid + i * 512;
        larow[i] = id >> 3;
        lau8[i]  = (id & 7) * 8;
        lasw[i]  = (uint32_t)(larow[i] * 128 + (((id & 7) ^ (larow[i] & 7)) << 4));
        lbrow[i] = id >> 4;
        int bu   = id & 15;
        lbu8[i]  = bu * 8;
        lbsw[i]  = (uint32_t)(lbrow[i] * 256 + (((bu & 8) | ((bu & 7) ^ (lbrow[i] & 7))) << 4));
    }

#define ISSUE_STAGE(kt)                                                        \
    do {                                                                       \
        const uint32_t sA = smemBase + ((kt) & (STAGES - 1)) * STAGEB;         \
        const uint32_t sB = sA + ABYTES;                                       \
        _Pragma("unroll")                                                      \
        for (int i = 0; i < 2; i++) {                                          \
            CP_ASYNC16(sA + lasw[i],                                           \
                       A + (size_t)(m0 + larow[i]) * lda + (kt) * 64 + lau8[i]); \
            CP_ASYNC16(sB + lbsw[i],                                           \
                       B + (size_t)((kt) * 64 + lbrow[i]) * ldb + n0 + lbu8[i]); \
        }                                                                      \
        CP_COMMIT();                                                           \
    } while (0)

    // A fragment addresses (normal ldmatrix)
    const int r7 = lane & 7;
    const int b3 = (lane >> 3) & 1;
    const int b4 = (lane >> 4) & 1;
    uint32_t rowA[2], unitA[4];
#pragma unroll
    for (int m = 0; m < 2; m++) rowA[m] = (uint32_t)((wm + m * 16 + b3 * 8 + r7) * 128);
#pragma unroll
    for (int ks = 0; ks < 4; ks++) unitA[ks] = (uint32_t)(((2 * ks + b4) ^ r7) << 4);

    // B fragment addresses (trans ldmatrix): p over 2 d16 tiles
    const int mi = lane >> 3;
    const int kb = (mi & 1) * 8 + r7;
    uint32_t btoff[2];
#pragma unroll
    for (int p = 0; p < 2; p++) {
        int u = ((wn + p * 16 + (mi >> 1) * 8) >> 3);
        btoff[p] = (uint32_t)(kb * 256 + (((u & 8) | ((u & 7) ^ r7)) << 4));
    }

    float acc[2][4][4];
#pragma unroll
    for (int m = 0; m < 2; m++)
#pragma unroll
        for (int n = 0; n < 4; n++)
#pragma unroll
            for (int q = 0; q < 4; q++) acc[m][n][q] = 0.f;

    for (int s = 0; s < STAGES - 1 && s < nkt; s++) ISSUE_STAGE(s);

    for (int kt = 0; kt < nkt; kt++) {
        CP_WAIT(STAGES - 2);
        __syncthreads();
        if (kt + STAGES - 1 < nkt) ISSUE_STAGE(kt + STAGES - 1);

        const uint32_t sA = smemBase + (kt & (STAGES - 1)) * STAGEB;
        const uint32_t sB = sA + ABYTES;

#pragma unroll
        for (int ks = 0; ks < 4; ks++) {
            uint32_t af[2][4];
            LDSM_X4(af[0], sA + rowA[0] + unitA[ks]);
            LDSM_X4(af[1], sA + rowA[1] + unitA[ks]);
            uint32_t bfr[2][4];
#pragma unroll
            for (int p = 0; p < 2; p++)
                LDSM_X4_T(bfr[p], sB + ks * 4096 + btoff[p]);
#pragma unroll
            for (int m = 0; m < 2; m++)
#pragma unroll
                for (int n = 0; n < 4; n++)
                    MMA_F16(acc[m][n], af[m], &bfr[n >> 1][(n & 1) * 2]);
        }
    }

#pragma unroll
    for (int m = 0; m < 2; m++) {
        const int r0 = m0 + wm + m * 16 + g;
#pragma unroll
        for (int n = 0; n < 4; n++) {
            const int col = n0 + wn + n * 8 + 2 * tg;
            if (outHalf) {
                __half* C = (__half*)Cv;
                *(uint32_t*)(C + (size_t)r0 * ldc + col) =
                    pack_h2(acc[m][n][0], acc[m][n][1]);
                *(uint32_t*)(C + (size_t)(r0 + 8) * ldc + col) =
                    pack_h2(acc[m][n][2], acc[m][n][3]);
            } else {
                float* C = (float*)Cv;
                *(float2*)(C + (size_t)r0 * ldc + col) =
                    make_float2(acc[m][n][0], acc[m][n][1]);
                *(float2*)(C + (size_t)(r0 + 8) * ldc + col) =
                    make_float2(acc[m][n][2], acc[m][n][3]);
            }
        }
    }
#undef ISSUE_STAGE
}

// ---------------------------------------------------------------------------
// Fused causal flash attention (fp16 mma, fp32 accum). Unchanged from R11.
// ---------------------------------------------------------------------------
#define FSM_Q 0
#define FSM_P 32768
#define FSM_R 65536
#define FSM_TOTAL (128 * 1024)

__global__ void __launch_bounds__(256, 1) flash_attn()
{
    extern __shared__ char smem[];
    const uint32_t sb = smem_u32(smem);

    const int h     = blockIdx.y;
    const int itile = (int)gridDim.x - 1 - (int)blockIdx.x;
    const int kvh   = h >> 2;
    const int tid   = threadIdx.x;
    const int lane  = tid & 31;
    const int wid   = tid >> 5;
    const int g     = lane >> 2, tg = lane & 3;
    const int wr    = wid * 16;

    int lrow[4], lu8[4], vrow[4], vu8[4];
    uint32_t lsw[4], vsw[4];
#pragma unroll
    for (int i = 0; i < 4; i++) {
        int id = tid + i * 256;
        lrow[i] = id >> 3;
        lu8[i]  = (id & 7) * 8;
        lsw[i]  = (uint32_t)(lrow[i] * 128 + (((id & 7) ^ (lrow[i] & 7)) << 4));
        vrow[i] = id >> 4;
        int vu  = id & 15;
        vu8[i]  = vu * 8;
        vsw[i]  = (uint32_t)(vrow[i] * 256 + (((vu & 8) | ((vu & 7) ^ (vrow[i] & 7))) << 4));
    }

    const __half* Qg = g_qkv + (size_t)(itile * 128) * QKVN + h * HD;
    const __half* Kg = g_qkv + KOFF + (size_t)kvh * HD;
    const __half* Vg = g_qkv + VOFF + (size_t)kvh * HD;

#pragma unroll
    for (int kt = 0; kt < 2; kt++)
#pragma unroll
        for (int i = 0; i < 4; i++)
            CP_ASYNC16(sb + FSM_Q + kt * 16384 + lsw[i],
                       Qg + (size_t)lrow[i] * QKVN + kt * 64 + lu8[i]);
    CP_COMMIT();

    const int nch = 4 * (itile + 1);

#define ISSUE_CHUNK(c)                                                         \
    do {                                                                       \
        const int _jt = (c) >> 2, _ty = ((c) >> 1) & 1, _kt = (c) & 1;         \
        const uint32_t _dst = sb + FSM_R + ((c) & 3) * 16384;                  \
        if (_ty == 0) {                                                        \
            _Pragma("unroll")                                                  \
            for (int i = 0; i < 4; i++)                                        \
                CP_ASYNC16(_dst + lsw[i],                                      \
                           Kg + (size_t)(_jt * 128 + lrow[i]) * QKVN + _kt * 64 + lu8[i]); \
        } else {                                                               \
            _Pragma("unroll")                                                  \
            for (int i = 0; i < 4; i++)                                        \
                CP_ASYNC16(_dst + vsw[i],                                      \
                           Vg + (size_t)(_jt * 128 + _kt * 64 + vrow[i]) * QKVN + vu8[i]); \
        }                                                                      \
        CP_COMMIT();                                                           \
    } while (0)

    for (int c = 0; c < 3; c++) ISSUE_CHUNK(c);

    const int r7 = lane & 7;
    const int b3 = (lane >> 3) & 1;
    const int b4 = (lane >> 4) & 1;
    const uint32_t rowAf = (uint32_t)((wr + b3 * 8 + r7) * 128);
    uint32_t rowB[8], unitA[4], unitB[4];
#pragma unroll
    for (int p = 0; p < 8; p++) rowB[p] = (uint32_t)(((2 * p + b4) * 8 + r7) * 128);
#pragma unroll
    for (int ks = 0; ks < 4; ks++) {
        unitA[ks] = (uint32_t)(((2 * ks + b4) ^ r7) << 4);
        unitB[ks] = (uint32_t)(((2 * ks + b3) ^ r7) << 4);
    }
    const int mi = lane >> 3;
    const int kb = (mi & 1) * 8 + r7;
    uint32_t vtoff[8];
#pragma unroll
    for (int p = 0; p < 8; p++) {
        int u = 2 * p + (mi >> 1);
        vtoff[p] = (uint32_t)(kb * 256 + (((u & 8) | ((u & 7) ^ r7)) << 4));
    }

    float S[16][4], O[16][4];
#pragma unroll
    for (int n = 0; n < 16; n++)
#pragma unroll
        for (int q = 0; q < 4; q++) O[n][q] = 0.f;
    float mrow0 = -1e30f, mrow1 = -1e30f;
    float lsum0 = 0.f, lsum1 = 0.f;

    const int rl0 = wr + g;
    const int rl1 = wr + g + 8;
    const float scl = 0.08838834764831845f;

    for (int c = 0; c < nch; c++) {
        CP_WAIT(2);
        __syncthreads();
        if (c + 3 < nch) ISSUE_CHUNK(c + 3);

        const int jt = c >> 2, ty = (c >> 1) & 1, kt = c & 1;
        const uint32_t sBb = sb + FSM_R + (c & 3) * 16384;

        if (ty == 0) {
            if (kt == 0) {
#pragma unroll
                for (int n = 0; n < 16; n++)
#pragma unroll
                    for (int q = 0; q < 4; q++) S[n][q] = 0.f;
            }
            const uint32_t sAq = sb + FSM_Q + kt * 16384;
#pragma unroll
            for (int ks = 0; ks < 4; ks++) {
                uint32_t af[4];
                LDSM_X4(af, sAq + rowAf + unitA[ks]);
                uint32_t bfr[8][4];
#pragma unroll
                for (int p = 0; p < 8; p++) LDSM_X4(bfr[p], sBb + rowB[p] + unitB[ks]);
#pragma unroll
                for (int n = 0; n < 16; n++)
                    MMA_F16(S[n], af, &bfr[n >> 1][(n & 1) * 2]);
            }

            if (kt == 1) {
#pragma unroll
                for (int n = 0; n < 16; n++)
#pragma unroll
                    for (int q = 0; q < 4; q++) S[n][q] *= scl;

                if (jt == itile) {
#pragma unroll
                    for (int n = 0; n < 16; n++) {
                        const int c0 = n * 8 + 2 * tg;
                        if (c0 > rl0)     S[n][0] = -1e30f;
                        if (c0 + 1 > rl0) S[n][1] = -1e30f;
                        if (c0 > rl1)     S[n][2] = -1e30f;
                        if (c0 + 1 > rl1) S[n][3] = -1e30f;
                    }
                }

                float tm0 = -1e30f, tm1 = -1e30f;
#pragma unroll
                for (int n = 0; n < 16; n++) {
                    tm0 = fmaxf(tm0, fmaxf(S[n][0], S[n][1]));
                    tm1 = fmaxf(tm1, fmaxf(S[n][2], S[n][3]));
                }
                tm0 = fmaxf(tm0, __shfl_xor_sync(0xFFFFFFFF, tm0, 1));
                tm0 = fmaxf(tm0, __shfl_xor_sync(0xFFFFFFFF, tm0, 2));
                tm1 = fmaxf(tm1, __shfl_xor_sync(0xFFFFFFFF, tm1, 1));
                tm1 = fmaxf(tm1, __shfl_xor_sync(0xFFFFFFFF, tm1, 2));

                const float mn0 = fmaxf(mrow0, tm0);
                const float mn1 = fmaxf(mrow1, tm1);
                const float a0 = __expf(mrow0 - mn0);
                const float a1 = __expf(mrow1 - mn1);
                mrow0 = mn0; mrow1 = mn1;

                float s0 = 0.f, s1 = 0.f;
#pragma unroll
                for (int n = 0; n < 16; n++) {
                    S[n][0] = __expf(S[n][0] - mn0);
                    S[n][1] = __expf(S[n][1] - mn0);
                    S[n][2] = __expf(S[n][2] - mn1);
                    S[n][3] = __expf(S[n][3] - mn1);
                    s0 += S[n][0] + S[n][1];
                    s1 += S[n][2] + S[n][3];
                }
                s0 += __shfl_xor_sync(0xFFFFFFFF, s0, 1);
                s0 += __shfl_xor_sync(0xFFFFFFFF, s0, 2);
                s1 += __shfl_xor_sync(0xFFFFFFFF, s1, 1);
                s1 += __shfl_xor_sync(0xFFFFFFFF, s1, 2);
                lsum0 = lsum0 * a0 + s0;
                lsum1 = lsum1 * a1 + s1;

#pragma unroll
                for (int n = 0; n < 16; n++) {
                    O[n][0] *= a0; O[n][1] *= a0;
                    O[n][2] *= a1; O[n][3] *= a1;
                }

#pragma unroll
                for (int n = 0; n < 16; n++) {
                    const uint32_t a =
                        sb + FSM_P + ((n >> 3) * 16384) + rl0 * 128 +
                        (((n & 7) ^ (rl0 & 7)) << 4) + tg * 4;
                    STSU32(a, pack_h2(S[n][0], S[n][1]));
                    STSU32(a + 1024, pack_h2(S[n][2], S[n][3]));
                }
            }
        } else {
            const uint32_t sAp = sb + FSM_P + kt * 16384;
#pragma unroll
            for (int ks = 0; ks < 4; ks++) {
                uint32_t af[4];
                LDSM_X4(af, sAp + rowAf + unitA[ks]);
                uint32_t bfr[8][4];
#pragma unroll
                for (int p = 0; p < 8; p++)
                    LDSM_X4_T(bfr[p], sBb + ks * 4096 + vtoff[p]);
#pragma unroll
                for (int n = 0; n < 16; n++)
                    MMA_F16(O[n], af, &bfr[n >> 1][(n & 1) * 2]);
            }
        }
    }
#undef ISSUE_CHUNK

    const float inv0 = 1.0f / lsum0;
    const float inv1 = 1.0f / lsum1;
    const int gr0 = itile * 128 + rl0;
    const int gr1 = itile * 128 + rl1;
#pragma unroll
    for (int n = 0; n < 16; n++) {
        const int col = h * HD + n * 8 + 2 * tg;
        *(uint32_t*)(g_attn + (size_t)gr0 * DIMC + col) =
            pack_h2(O[n][0] * inv0, O[n][1] * inv0);
        *(uint32_t*)(g_attn + (size_t)gr1 * DIMC + col) =
            pack_h2(O[n][2] * inv1, O[n][3] * inv1);
    }
}

// ---------------------------------------------------------------------------
// Fused fp32 -> fp16 convert for x, W_qkv, W_o (float4 granules)
// ---------------------------------------------------------------------------
#define N4_X  (TSEQ * DIMC / 4)
#define N4_W1 (DIMC * QKVN / 4)
#define N4_W2 (DIMC * DIMC / 4)

__global__ void k_cvt_all(const float* __restrict__ sx,
                          const float* __restrict__ sw1,
                          const float* __restrict__ sw2)
{
    int i = blockIdx.x * blockDim.x + threadIdx.x;
    const float* src;
    __half* dst;
    int off;
    if (i < N4_X)              { src = sx;  dst = g_x;    off = i; }
    else if (i < N4_X + N4_W1) { src = sw1; dst = g_wqkv; off = i - N4_X; }
    else if (i < N4_X + N4_W1 + N4_W2) { src = sw2; dst = g_wo; off = i - N4_X - N4_W1; }
    else return;
    float4 v = ((const float4*)src)[off];
    uint2 o;
    o.x = pack_h2(v.x, v.y);
    o.y = pack_h2(v.z, v.w);
    ((uint2*)dst)[off] = o;
}

// ---------------------------------------------------------------------------
// Host side
// ---------------------------------------------------------------------------
extern "C" void kernel_launch(void* const* d_in, const int* in_sizes, int n_in,
                              void* d_out, int out_size)
{
    const float* x    = (const float*)d_in[0];
    const float* Wqkv = (const float*)d_in[1];
    const float* Wo   = (const float*)d_in[2];

    void *px, *pwqkv, *pwo, *pqkv, *pattn;
    cudaGetSymbolAddress(&px, g_x);
    cudaGetSymbolAddress(&pwqkv, g_wqkv);
    cudaGetSymbolAddress(&pwo, g_wo);
    cudaGetSymbolAddress(&pqkv, g_qkv);
    cudaGetSymbolAddress(&pattn, g_attn);

    const int smemSz = STAGES * STAGEB;   // 128 KB
    cudaFuncSetAttribute(gemm_h, cudaFuncAttributeMaxDynamicSharedMemorySize, smemSz);
    cudaFuncSetAttribute(flash_attn, cudaFuncAttributeMaxDynamicSharedMemorySize, FSM_TOTAL);

    // 1) fused fp32 -> fp16 conversion (x, W_qkv, W_o)
    {
        const int total = N4_X + N4_W1 + N4_W2;
        k_cvt_all<<<(total + 255) / 256, 256>>>(x, Wqkv, Wo);
    }

    // 2) qkv = x_h @ W_qkv  [2048,3072] (fp16 out)
    gemm_h<<<dim3(QKVN / 128, TSEQ / 128), 512, smemSz>>>(
        (const __half*)px, DIMC, (const __half*)pwqkv, QKVN,
        pqkv, QKVN, DIMC, 1);

    // 3) fused causal attention -> g_attn (fp16)
    flash_attn<<<dim3(TSEQ / 128, NH), 256, FSM_TOTAL>>>();

    // 4) out = attn @ W_o (fp32 out)
    gemm_h<<<dim3(DIMC / 128, TSEQ / 128), 512, smemSz>>>(
        (const __half*)pattn, DIMC, (const __half*)pwo, DIMC,
        d_out, DIMC, DIMC, 0);
}